// round 15
// baseline (speedup 1.0000x reference)
#include <cuda_runtime.h>

#define FULL 0xffffffffu

// LISTA v11 = R9 + warp-uniform conv params moved to __constant__ memory
// (filled per-launch via graph-capturable D2D cudaMemcpyToSymbolAsync).
// Uniform imm-offset reads -> LDCU/UR operands on the uniform-const port,
// OFF the MIO queue. MIO ops/stage: 21 -> 15 (cross-round regression shows
// per-stage time tracks MIO count at ~12 cyc/op).
// lane = h*16 + c*8 + i; warp = one column; 16 blocks x 128 threads.

__constant__ float g_c1w[144];
__constant__ float g_c1b[48];
__constant__ float g_c2w[144];
__constant__ float g_c2b[16];
__constant__ float g_thr[16];

__global__ void __launch_bounds__(128, 1) lista_kernel(
    const float* __restrict__ y_real, const float* __restrict__ y_imag,
    const float* __restrict__ w1_real, const float* __restrict__ w1_imag,
    const float* __restrict__ w2_real, const float* __restrict__ w2_imag,
    float* __restrict__ out)
{
    __shared__ __align__(16) float s_w2r [1024];   // w2_real, 16 stages
    __shared__ __align__(16) float s_w2ip[1024];   // +w2_imag (c=1)
    __shared__ __align__(16) float s_w2in[1024];   // -w2_imag (c=0)

    const int tid  = threadIdx.x;          // 0..127
    const int lane = tid & 31;
    const int i    = lane & 7;
    const int c    = (lane >> 3) & 1;
    const int h    = lane >> 4;
    const int b    = (int)blockIdx.x * 4 + (tid >> 5);   // batch column

    // ---- staging: W2 tables (+/- imag) only; conv params via constants ----
    {
        const float4* gr = (const float4*)w2_real;
        const float4* gi = (const float4*)w2_imag;
        #pragma unroll
        for (int k = tid; k < 256; k += 128) {
            float4 vr = gr[k];
            float4 vi = gi[k];
            ((float4*)s_w2r )[k] = vr;
            ((float4*)s_w2ip)[k] = vi;
            ((float4*)s_w2in)[k] = make_float4(-vi.x, -vi.y, -vi.z, -vi.w);
        }
    }

    // ---- y half-slices (own comp + sign-folded opposite) ----
    const float sgn = c ? 1.f : -1.f;   // z_r: -wi*x_i ; z_i: +wi*x_r
    float yc[4], yos[4];
    {
        const float* yc_ptr = c ? y_imag : y_real;
        const float* yo_ptr = c ? y_real : y_imag;
        #pragma unroll
        for (int j4 = 0; j4 < 4; j4++) {
            int j = h * 4 + j4;
            yc[j4]  = yc_ptr[j * 64 + b];
            yos[j4] = sgn * yo_ptr[j * 64 + b];
        }
    }

    // ---- precompute 16 stage HALF-biases (W1[s] y), this j-half ----
    float bias[16];
    #pragma unroll
    for (int s = 0; s < 16; s++) {
        const float4 wr = *(const float4*)(w1_real + s * 64 + i * 8 + h * 4);
        const float4 wi = *(const float4*)(w1_imag + s * 64 + i * 8 + h * 4);
        float a0 = 0.f, a1 = 0.f;
        a0 = fmaf(wr.x, yc[0], a0); a1 = fmaf(wi.x, yos[0], a1);
        a0 = fmaf(wr.y, yc[1], a0); a1 = fmaf(wi.y, yos[1], a1);
        a0 = fmaf(wr.z, yc[2], a0); a1 = fmaf(wi.z, yos[2], a1);
        a0 = fmaf(wr.w, yc[3], a0); a1 = fmaf(wi.w, yos[3], a1);
        bias[s] = a0 + a1;
    }

    __syncthreads();

    // ---- static pointers (loop body: LDS [ptr + imm] + constants) ----
    const float* pw_r = s_w2r + i * 8 + h * 4;
    const float* pw_i = (c ? s_w2ip : s_w2in) + i * 8 + h * 4;
    const bool   e0 = (i > 0), e2 = (i < 7);

    // ---- init: x = soft(full bias[0], thr[0]) ----
    float x;
    {
        const float b0 = bias[0] + __shfl_xor_sync(FULL, bias[0], 16);
        const float t0 = g_thr[0];
        x = b0 - fminf(fmaxf(b0, -t0), t0);
    }

    const int src_c = (c << 3);        // lanes holding own-comp x_j
    const int src_o = ((c ^ 1) << 3);  // lanes holding opposite-comp x_j
    const int nbase = lane & 24;       // keep (c,h) bits for neighbor shfl

    // ---- 16 sequential stages (fully unrolled: const offsets are imm) ----
    #pragma unroll
    for (int s = 0; s < 16; s++) {
        // broadcast x for this thread's j-half
        float xc[4], xo[4];
        #pragma unroll
        for (int j4 = 0; j4 < 4; j4++) {
            int j = h * 4 + j4;
            xc[j4] = __shfl_sync(FULL, x, src_c + j);
            xo[j4] = __shfl_sync(FULL, x, src_o + j);
        }

        // half dot from shared weight tables (only divergent loads left)
        const float4 wr = *(const float4*)(pw_r + s * 64);
        const float4 wi = *(const float4*)(pw_i + s * 64);
        float a0 = bias[s], a1 = 0.f;
        a0 = fmaf(wr.x, xc[0], a0); a1 = fmaf(wi.x, xo[0], a1);
        a0 = fmaf(wr.y, xc[1], a0); a1 = fmaf(wi.y, xo[1], a1);
        a0 = fmaf(wr.z, xc[2], a0); a1 = fmaf(wi.z, xo[2], a1);
        a0 = fmaf(wr.w, xc[3], a0); a1 = fmaf(wi.w, xo[3], a1);
        const float a = a0 + a1;
        const float z = a + __shfl_xor_sync(FULL, a, 16);  // full bias+dot

        // z neighbors at +-1,+-2 (same component, zero-padded via SEL)
        float zv[5];
        zv[2] = z;
        float zm2 = __shfl_sync(FULL, z, nbase | ((i - 2) & 7));
        float zm1 = __shfl_sync(FULL, z, nbase | ((i - 1) & 7));
        float zp1 = __shfl_sync(FULL, z, nbase | ((i + 1) & 7));
        float zp2 = __shfl_sync(FULL, z, nbase | ((i + 2) & 7));
        zv[0] = (i >= 2) ? zm2 : 0.f;
        zv[1] = (i >= 1) ? zm1 : 0.f;
        zv[3] = (i <= 6) ? zp1 : 0.f;
        zv[4] = (i <= 5) ? zp2 : 0.f;

        // conv params from CONSTANT memory (warp-uniform, imm offsets ->
        // uniform-const port / UR operands, not MIO)
        const float k1_00 = g_c1w[s * 9 + 0], k1_01 = g_c1w[s * 9 + 1], k1_02 = g_c1w[s * 9 + 2];
        const float k1_10 = g_c1w[s * 9 + 3], k1_11 = g_c1w[s * 9 + 4], k1_12 = g_c1w[s * 9 + 5];
        const float k1_20 = g_c1w[s * 9 + 6], k1_21 = g_c1w[s * 9 + 7], k1_22 = g_c1w[s * 9 + 8];
        const float bb0 = g_c1b[s * 3 + 0], bb1v = g_c1b[s * 3 + 1], bb2 = g_c1b[s * 3 + 2];
        const float k2_00 = e0 ? g_c2w[s * 9 + 0] : 0.f;
        const float k2_01 =      g_c2w[s * 9 + 1];
        const float k2_02 = e2 ? g_c2w[s * 9 + 2] : 0.f;
        const float k2_10 = e0 ? g_c2w[s * 9 + 3] : 0.f;
        const float k2_11 =      g_c2w[s * 9 + 4];
        const float k2_12 = e2 ? g_c2w[s * 9 + 5] : 0.f;
        const float k2_20 = e0 ? g_c2w[s * 9 + 6] : 0.f;
        const float k2_21 =      g_c2w[s * 9 + 7];
        const float k2_22 = e2 ? g_c2w[s * 9 + 8] : 0.f;
        const float cb2 = g_c2b[s];
        const float t   = g_thr[s];
        const float tn  = -t;

        const float k1[3][3] = {{k1_00, k1_01, k1_02},
                                {k1_10, k1_11, k1_12},
                                {k1_20, k1_21, k1_22}};
        const float k2m[3][3] = {{k2_00, k2_01, k2_02},
                                 {k2_10, k2_11, k2_12},
                                 {k2_20, k2_21, k2_22}};
        const float bbv[3] = {bb0, bb1v, bb2};

        // conv1 + 3-op soft at pos i-1, i, i+1; conv2 with 3 accumulators
        float o0 = cb2, o1 = 0.f, o2 = 0.f;
        #pragma unroll
        for (int ch = 0; ch < 3; ch++) {
            const float w0 = k1[ch][0], w1 = k1[ch][1], w2 = k1[ch][2];
            const float bb = bbv[ch];
            float v0 = bb, v1 = bb, v2 = bb;
            v0 = fmaf(w0, zv[0], v0); v1 = fmaf(w0, zv[1], v1); v2 = fmaf(w0, zv[2], v2);
            v0 = fmaf(w1, zv[1], v0); v1 = fmaf(w1, zv[2], v1); v2 = fmaf(w1, zv[3], v2);
            v0 = fmaf(w2, zv[2], v0); v1 = fmaf(w2, zv[3], v1); v2 = fmaf(w2, zv[4], v2);
            const float s0 = v0 - fminf(fmaxf(v0, tn), t);
            const float s1 = v1 - fminf(fmaxf(v1, tn), t);
            const float s2 = v2 - fminf(fmaxf(v2, tn), t);
            o0 = fmaf(k2m[ch][0], s0, o0);
            o1 = fmaf(k2m[ch][1], s1, o1);
            o2 = fmaf(k2m[ch][2], s2, o2);
        }
        x = (o0 + o1) + o2;
    }

    // out: x_r (8,64) then x_i (8,64); h=0 lanes write
    if (h == 0) out[c * 512 + i * 64 + b] = x;
}

extern "C" void kernel_launch(void* const* d_in, const int* in_sizes, int n_in,
                              void* d_out, int out_size) {
    (void)in_sizes; (void)n_in; (void)out_size;
    const float* y_real  = (const float*)d_in[0];
    const float* y_imag  = (const float*)d_in[1];
    const float* w1_real = (const float*)d_in[2];
    const float* w1_imag = (const float*)d_in[3];
    const float* w2_real = (const float*)d_in[4];
    const float* w2_imag = (const float*)d_in[5];
    float* out = (float*)d_out;

    // warp-uniform per-stage params -> constant bank (D2D async: graph-OK,
    // allocation-free, deterministic; re-copied on every replay)
    cudaMemcpyToSymbolAsync(g_thr, d_in[6], 16 * sizeof(float), 0,
                            cudaMemcpyDeviceToDevice);
    cudaMemcpyToSymbolAsync(g_c1w, d_in[7], 144 * sizeof(float), 0,
                            cudaMemcpyDeviceToDevice);
    cudaMemcpyToSymbolAsync(g_c1b, d_in[8], 48 * sizeof(float), 0,
                            cudaMemcpyDeviceToDevice);
    cudaMemcpyToSymbolAsync(g_c2w, d_in[9], 144 * sizeof(float), 0,
                            cudaMemcpyDeviceToDevice);
    cudaMemcpyToSymbolAsync(g_c2b, d_in[10], 16 * sizeof(float), 0,
                            cudaMemcpyDeviceToDevice);

    lista_kernel<<<16, 128>>>(y_real, y_imag, w1_real, w1_imag,
                              w2_real, w2_imag, out);
}

// round 16
// speedup vs baseline: 1.9446x; 1.9446x over previous
#include <cuda_runtime.h>

#define FULL 0xffffffffu

// LISTA R5 (wall-record kernel, resubmitted verbatim for reproducibility).
// lane = h*16 + c*8 + i (h = j-half, c = re/im, i = position); warp=column.
// Per-stage: 8 shfl (x broadcast) -> 8 FMA half-dot -> 1 shfl_xor reduce
// -> 4 shfl z-neighbors -> local conv1 at i-1,i,i+1 -> conv2.
// W1[s]@y HALF-biases precomputed into registers. 16 blocks x 128 threads.

__global__ void __launch_bounds__(128, 1) lista_kernel(
    const float* __restrict__ y_real, const float* __restrict__ y_imag,
    const float* __restrict__ w1_real, const float* __restrict__ w1_imag,
    const float* __restrict__ w2_real, const float* __restrict__ w2_imag,
    const float* __restrict__ thr,
    const float* __restrict__ c1w, const float* __restrict__ c1b,
    const float* __restrict__ c2w, const float* __restrict__ c2b,
    float* __restrict__ out)
{
    // conv params staged into shared, padded + aligned for LDS.128
    __shared__ __align__(16) float s_c1w[16 * 12];   // 9 used + 3 pad per stage
    __shared__ __align__(16) float s_c1b[16 * 4];    // 3 used + 1 pad
    __shared__ __align__(16) float s_c2w[16 * 12];
    __shared__ __align__(16) float s_misc[16 * 2];   // {c2b[s], thr[s]}

    const int tid  = threadIdx.x;          // 0..127
    const int lane = tid & 31;
    const int i    = lane & 7;
    const int c    = (lane >> 3) & 1;
    const int h    = lane >> 4;
    const int b    = (int)blockIdx.x * 4 + (tid >> 5);   // batch column
    const float sgn = c ? 1.f : -1.f;   // zr uses -w_i*x_i ; zi uses +w_i*x_r

    // ---- one-time staging of conv params (padded, aligned) ----
    for (int k = tid; k < 192; k += 128) {
        int s = k / 12, r = k - s * 12;
        s_c1w[k] = (r < 9) ? c1w[s * 9 + r] : 0.f;
        s_c2w[k] = (r < 9) ? c2w[s * 9 + r] : 0.f;
    }
    if (tid < 64) {
        int s = tid >> 2, r = tid & 3;
        s_c1b[tid] = (r < 3) ? c1b[s * 3 + r] : 0.f;
    }
    if (tid < 32) {
        int s = tid >> 1;
        s_misc[tid] = (tid & 1) ? thr[s] : c2b[s];
    }

    // ---- y slice for this thread's j-half (own comp + signed opposite) ----
    float yc[4], yos[4];
    {
        const float* yc_ptr = c ? y_imag : y_real;
        const float* yo_ptr = c ? y_real : y_imag;
        #pragma unroll
        for (int j4 = 0; j4 < 4; j4++) {
            int j = h * 4 + j4;
            yc[j4]  = yc_ptr[j * 64 + b];
            yos[j4] = sgn * yo_ptr[j * 64 + b];
        }
    }

    // ---- precompute all 16 stage HALF-biases (W1[s] y)_{i,c}, this j-half.
    float bias[16];
    #pragma unroll
    for (int s = 0; s < 16; s++) {
        const float4 wr = *(const float4*)(w1_real + s * 64 + i * 8 + h * 4);
        const float4 wi = *(const float4*)(w1_imag + s * 64 + i * 8 + h * 4);
        float a = 0.f;
        a = fmaf(wr.x, yc[0], a); a = fmaf(wi.x, yos[0], a);
        a = fmaf(wr.y, yc[1], a); a = fmaf(wi.y, yos[1], a);
        a = fmaf(wr.z, yc[2], a); a = fmaf(wi.z, yos[2], a);
        a = fmaf(wr.w, yc[3], a); a = fmaf(wi.w, yos[3], a);
        bias[s] = a;                       // half-sum only
    }

    __syncthreads();

    // ---- init: x = soft(full bias[0], thr[0]) ----
    float x;
    {
        const float b0 = bias[0] + __shfl_xor_sync(FULL, bias[0], 16);
        const float t0 = s_misc[1];
        x = fmaxf(b0 - t0, 0.f) + fminf(b0 + t0, 0.f);
    }

    const int src_c = (c << 3);        // lanes holding own-comp x_j
    const int src_o = ((c ^ 1) << 3);  // lanes holding opposite-comp x_j
    const int nbase = lane & 24;       // keep (c,h) bits for neighbor shfl

    // ---- 16 sequential stages (fully unrolled) ----
    #pragma unroll
    for (int s = 0; s < 16; s++) {
        // broadcast x for this thread's j-half
        float xc[4], xos[4];
        #pragma unroll
        for (int j4 = 0; j4 < 4; j4++) {
            int j = h * 4 + j4;
            xc[j4]  = __shfl_sync(FULL, x, src_c + j);
            xos[j4] = sgn * __shfl_sync(FULL, x, src_o + j);
        }

        // half dot: a = half-bias + sum_j w2r*xc + w2i*(sgn*xo)
        const float4 wr = *(const float4*)(w2_real + s * 64 + i * 8 + h * 4);
        const float4 wi = *(const float4*)(w2_imag + s * 64 + i * 8 + h * 4);
        float a = bias[s];
        a = fmaf(wr.x, xc[0], a); a = fmaf(wi.x, xos[0], a);
        a = fmaf(wr.y, xc[1], a); a = fmaf(wi.y, xos[1], a);
        a = fmaf(wr.z, xc[2], a); a = fmaf(wi.z, xos[2], a);
        a = fmaf(wr.w, xc[3], a); a = fmaf(wi.w, xos[3], a);
        float z = a + __shfl_xor_sync(FULL, a, 16);   // completes bias + dot

        // z neighbors at +-1, +-2 (same component, zero-padded)
        float zv[5];
        zv[2] = z;
        float zm2 = __shfl_sync(FULL, z, nbase | ((i - 2) & 7));
        float zm1 = __shfl_sync(FULL, z, nbase | ((i - 1) & 7));
        float zp1 = __shfl_sync(FULL, z, nbase | ((i + 1) & 7));
        float zp2 = __shfl_sync(FULL, z, nbase | ((i + 2) & 7));
        zv[0] = (i >= 2) ? zm2 : 0.f;
        zv[1] = (i >= 1) ? zm1 : 0.f;
        zv[3] = (i <= 6) ? zp1 : 0.f;
        zv[4] = (i <= 5) ? zp2 : 0.f;

        // conv params (shared, broadcast LDS.128)
        const float4 wa  = *(const float4*)(s_c1w + s * 12);
        const float4 wb  = *(const float4*)(s_c1w + s * 12 + 4);
        const float4 wcv = *(const float4*)(s_c1w + s * 12 + 8);
        const float4 b1  = *(const float4*)(s_c1b + s * 4);
        const float4 va  = *(const float4*)(s_c2w + s * 12);
        const float4 vb  = *(const float4*)(s_c2w + s * 12 + 4);
        const float4 vc  = *(const float4*)(s_c2w + s * 12 + 8);
        const float  cb2 = s_misc[s * 2];
        const float  t   = s_misc[s * 2 + 1];

        const float k1[3][3] = {{wa.x, wa.y, wa.z},
                                {wa.w, wb.x, wb.y},
                                {wb.z, wb.w, wcv.x}};
        const float k2[3][3] = {{va.x, va.y, va.z},
                                {va.w, vb.x, vb.y},
                                {vb.z, vb.w, vc.x}};
        const float bb1[3] = {b1.x, b1.y, b1.z};

        // conv1 + soft at positions i-1, i, i+1 computed locally,
        // then conv2 at i — no third shuffle wave.
        float o = cb2;
        #pragma unroll
        for (int p3 = 0; p3 < 3; p3++) {                 // pos = i-1+p3
            const bool valid = (p3 == 1) || ((p3 == 0) ? (i > 0) : (i < 7));
            #pragma unroll
            for (int ch = 0; ch < 3; ch++) {
                float v = bb1[ch];
                v = fmaf(k1[ch][0], zv[p3],     v);
                v = fmaf(k1[ch][1], zv[p3 + 1], v);
                v = fmaf(k1[ch][2], zv[p3 + 2], v);
                float st = fmaxf(v - t, 0.f) + fminf(v + t, 0.f);
                st = valid ? st : 0.f;                   // conv2 zero-padding
                o = fmaf(k2[ch][p3], st, o);
            }
        }
        x = o;
    }

    // out: x_r (8,64) then x_i (8,64); h=0 lanes write
    if (h == 0) out[c * 512 + i * 64 + b] = x;
}

extern "C" void kernel_launch(void* const* d_in, const int* in_sizes, int n_in,
                              void* d_out, int out_size) {
    (void)in_sizes; (void)n_in; (void)out_size;
    const float* y_real  = (const float*)d_in[0];
    const float* y_imag  = (const float*)d_in[1];
    const float* w1_real = (const float*)d_in[2];
    const float* w1_imag = (const float*)d_in[3];
    const float* w2_real = (const float*)d_in[4];
    const float* w2_imag = (const float*)d_in[5];
    const float* thr     = (const float*)d_in[6];
    const float* c1w     = (const float*)d_in[7];
    const float* c1b     = (const float*)d_in[8];
    const float* c2w     = (const float*)d_in[9];
    const float* c2b     = (const float*)d_in[10];
    float* out = (float*)d_out;

    lista_kernel<<<16, 128>>>(y_real, y_imag, w1_real, w1_imag,
                              w2_real, w2_imag, thr, c1w, c1b, c2w, c2b, out);
}